// round 1
// baseline (speedup 1.0000x reference)
#include <cuda_runtime.h>

// ---------------------------------------------------------------------------
// QuantizedActorMLP: x[B,17] -> fq_act -> L1(17->64)+fq_act -> L2(64->64)+fq_act
//                    -> L3(64->6) ; weights per-tensor int8 fake-quant.
// All matmuls are exact int8 dots scaled by (step * s_w); we use DP4A.
// ---------------------------------------------------------------------------

#define ACT_SCALE 1.33f
#define QMAXF     127.0f

// Packed quantized weights (int8 x4 per word), produced by prep_kernel.
__device__ int   gWQ1[64 * 5];    // [j][g] : W1 row j, inputs 4g..4g+3 (k>=17 padded 0)
__device__ int   gWQ2[64 * 16];   // [j][g] : W2 row j
__device__ int   gWQ3[6 * 16];    // [k][g] : W3 row k
__device__ float gG[3];           // step * s_w per layer

__device__ __forceinline__ int pack4(int q0, int q1, int q2, int q3) {
    unsigned r = (unsigned)(q0 & 0xFF)
               | ((unsigned)(q1 & 0xFF) << 8)
               | ((unsigned)(q2 & 0xFF) << 16)
               | ((unsigned)q3 << 24);
    return (int)r;
}

// ---------------------------------------------------------------------------
// Prep: per-tensor max-abs scales + int8 quantize + pack. One small block.
// ---------------------------------------------------------------------------
__global__ void prep_kernel(const float* __restrict__ W1,
                            const float* __restrict__ W2,
                            const float* __restrict__ W3) {
    __shared__ float red[256];
    __shared__ float sS[3];
    const int tid = threadIdx.x;

    const float* Ws[3]   = {W1, W2, W3};
    const int    nel[3]  = {64 * 17, 64 * 64, 6 * 64};

    for (int t = 0; t < 3; ++t) {
        float m = 0.0f;
        const float* W = Ws[t];
        for (int i = tid; i < nel[t]; i += 256) m = fmaxf(m, fabsf(W[i]));
        red[tid] = m;
        __syncthreads();
        for (int s = 128; s > 0; s >>= 1) {
            if (tid < s) red[tid] = fmaxf(red[tid], red[tid + s]);
            __syncthreads();
        }
        if (tid == 0) sS[t] = red[0] / QMAXF;
        __syncthreads();
    }

    const float s1 = sS[0], s2 = sS[1], s3 = sS[2];
    const float step = ACT_SCALE / QMAXF;
    if (tid == 0) {
        gG[0] = step * s1;
        gG[1] = step * s2;
        gG[2] = step * s3;
    }

    // Pack W1: 64 rows x 17 (pad to 20)
    for (int w = tid; w < 64 * 5; w += 256) {
        int j = w / 5, g = w % 5;
        int q[4];
#pragma unroll
        for (int b = 0; b < 4; ++b) {
            int k = 4 * g + b;
            int v = 0;
            if (k < 17) {
                float r = rintf(W1[j * 17 + k] / s1);
                r = fminf(fmaxf(r, -QMAXF), QMAXF);
                v = (int)r;
            }
            q[b] = v;
        }
        gWQ1[w] = pack4(q[0], q[1], q[2], q[3]);
    }
    // Pack W2: 64 x 64
    for (int w = tid; w < 64 * 16; w += 256) {
        int j = w / 16, g = w % 16;
        int q[4];
#pragma unroll
        for (int b = 0; b < 4; ++b) {
            float r = rintf(W2[j * 64 + 4 * g + b] / s2);
            r = fminf(fmaxf(r, -QMAXF), QMAXF);
            q[b] = (int)r;
        }
        gWQ2[w] = pack4(q[0], q[1], q[2], q[3]);
    }
    // Pack W3: 6 x 64
    for (int w = tid; w < 6 * 16; w += 256) {
        int k = w / 16, g = w % 16;
        int q[4];
#pragma unroll
        for (int b = 0; b < 4; ++b) {
            float r = rintf(W3[k * 64 + 4 * g + b] / s3);
            r = fminf(fmaxf(r, -QMAXF), QMAXF);
            q[b] = (int)r;
        }
        gWQ3[w] = pack4(q[0], q[1], q[2], q[3]);
    }
}

// ---------------------------------------------------------------------------
// Main fused MLP kernel: 256 rows per block, one row per thread, DP4A math.
// ---------------------------------------------------------------------------
__global__ __launch_bounds__(256) void mlp_kernel(
    const float* __restrict__ x,
    const float* __restrict__ b1,
    const float* __restrict__ b2,
    const float* __restrict__ b3,
    float* __restrict__ out, int B) {

    __shared__ float sx[256 * 17];
    __shared__ __align__(16) int sW1[64 * 5];
    __shared__ __align__(16) int sW2[64 * 16];
    __shared__ __align__(16) int sW3[6 * 16];
    __shared__ float sb1[64], sb2[64], sb3[8];
    __shared__ float sG[3];
    __shared__ __align__(16) float sout[256 * 6];

    const int tid  = threadIdx.x;
    const int base = blockIdx.x * 256;
    const int rows = min(256, B - base);

    // Stage input tile (coalesced) + weights + biases
    {
        const int n = rows * 17;
        const float* xg = x + base * 17;
        for (int i = tid; i < n; i += 256) sx[i] = xg[i];
        for (int i = tid; i < 320; i += 256) sW1[i] = gWQ1[i];
        for (int i = tid; i < 1024; i += 256) sW2[i] = gWQ2[i];
        if (tid < 96) sW3[tid] = gWQ3[tid];
        if (tid < 64) { sb1[tid] = b1[tid]; sb2[tid] = b2[tid]; }
        if (tid < 6) sb3[tid] = b3[tid];
        if (tid < 3) sG[tid] = gG[tid];
    }
    __syncthreads();

    if (tid < rows) {
        const float INVSTEP = QMAXF / ACT_SCALE;
        const float g1 = sG[0], g2 = sG[1], g3 = sG[2];
        const float* xr = sx + tid * 17;

        // ---- input fake-quant + pack to 5 words (17 vals, pad 0) ----
        int p0[5];
#pragma unroll
        for (int g = 0; g < 5; ++g) {
            int q[4];
#pragma unroll
            for (int b = 0; b < 4; ++b) {
                const int k = 4 * g + b;
                int v = 0;
                if (k < 17) {
                    float xc = fminf(fmaxf(xr[k], -ACT_SCALE), ACT_SCALE);
                    v = __float2int_rn(xc * INVSTEP);
                }
                q[b] = v;
            }
            p0[g] = pack4(q[0], q[1], q[2], q[3]);
        }

        // ---- layer 1: 17 -> 64, act fake-quant, pack ----
        int a1[16];
#pragma unroll
        for (int jw = 0; jw < 16; ++jw) {
            int q[4];
#pragma unroll
            for (int jj = 0; jj < 4; ++jj) {
                const int j = jw * 4 + jj;
                int acc = 0;
#pragma unroll
                for (int g = 0; g < 5; ++g) acc = __dp4a(p0[g], sW1[j * 5 + g], acc);
                float f = fmaf((float)acc, g1, sb1[j]);
                f = fminf(fmaxf(f, -ACT_SCALE), ACT_SCALE);
                q[jj] = __float2int_rn(f * INVSTEP);
            }
            a1[jw] = pack4(q[0], q[1], q[2], q[3]);
        }

        // ---- layer 2: 64 -> 64, act fake-quant, pack ----
        int a2[16];
#pragma unroll
        for (int jw = 0; jw < 16; ++jw) {
            int q[4];
#pragma unroll
            for (int jj = 0; jj < 4; ++jj) {
                const int j = jw * 4 + jj;
                int acc = 0;
                const int4* wr = (const int4*)(sW2 + j * 16);
#pragma unroll
                for (int g = 0; g < 4; ++g) {
                    const int4 w = wr[g];
                    acc = __dp4a(a1[g * 4 + 0], w.x, acc);
                    acc = __dp4a(a1[g * 4 + 1], w.y, acc);
                    acc = __dp4a(a1[g * 4 + 2], w.z, acc);
                    acc = __dp4a(a1[g * 4 + 3], w.w, acc);
                }
                float f = fmaf((float)acc, g2, sb2[j]);
                f = fminf(fmaxf(f, -ACT_SCALE), ACT_SCALE);
                q[jj] = __float2int_rn(f * INVSTEP);
            }
            a2[jw] = pack4(q[0], q[1], q[2], q[3]);
        }

        // ---- layer 3: 64 -> 6 (no act quant) ----
        float o[6];
#pragma unroll
        for (int k = 0; k < 6; ++k) {
            int acc = 0;
            const int4* wr = (const int4*)(sW3 + k * 16);
#pragma unroll
            for (int g = 0; g < 4; ++g) {
                const int4 w = wr[g];
                acc = __dp4a(a2[g * 4 + 0], w.x, acc);
                acc = __dp4a(a2[g * 4 + 1], w.y, acc);
                acc = __dp4a(a2[g * 4 + 2], w.z, acc);
                acc = __dp4a(a2[g * 4 + 3], w.w, acc);
            }
            o[k] = fmaf((float)acc, g3, sb3[k]);
        }
#pragma unroll
        for (int k = 0; k < 6; ++k) sout[tid * 6 + k] = o[k];
    }
    __syncthreads();

    // Coalesced output store
    float* og = out + base * 6;
    if (rows == 256) {
        float4* ov = (float4*)og;
        const float4* sv = (const float4*)sout;
        for (int i = tid; i < 384; i += 256) ov[i] = sv[i];
    } else {
        const int nf = rows * 6;
        for (int i = tid; i < nf; i += 256) og[i] = sout[i];
    }
}

extern "C" void kernel_launch(void* const* d_in, const int* in_sizes, int n_in,
                              void* d_out, int out_size) {
    const float* x  = (const float*)d_in[0];
    const float* W1 = (const float*)d_in[1];
    const float* b1 = (const float*)d_in[2];
    const float* W2 = (const float*)d_in[3];
    const float* b2 = (const float*)d_in[4];
    const float* W3 = (const float*)d_in[5];
    const float* b3 = (const float*)d_in[6];
    float* out = (float*)d_out;

    const int B = in_sizes[0] / 17;
    const int blocks = (B + 255) / 256;

    prep_kernel<<<1, 256>>>(W1, W2, W3);
    mlp_kernel<<<blocks, 256>>>(x, b1, b2, b3, out, B);
}

// round 2
// speedup vs baseline: 1.1362x; 1.1362x over previous
#include <cuda_runtime.h>

// ---------------------------------------------------------------------------
// QuantizedActorMLP: x[B,17] -> fq_act -> L1(17->64)+fq_act -> L2(64->64)+fq_act
//                    -> L3(64->6). All matmuls are exact int8 dots (DP4A).
// Round 2: weights in __constant__ (LDCU path, off L1), int8-packed input
// staging, L3 fused into L2 loop (kills a2[] regs), folded requant scales.
// ---------------------------------------------------------------------------

#define ACT_SCALE 1.33f
#define QMAXF     127.0f

struct QConst {
    int   W1[64 * 5];    // [j][g], K padded 17->20
    int   W2[64 * 16];   // [j][g]
    int   W3[6 * 16];    // [k][g]
    float b1s[64];       // b1/step
    float b2s[64];       // b2/step
    float b3[8];
    float G1, G2, G3;    // s1, s2, step*s3
};

__device__   QConst gQ;   // staging, written by prep_kernel
__constant__ QConst cQ;   // copied via cudaMemcpyToSymbolAsync

__device__ __forceinline__ int packq(int q0, int q1, int q2, int q3) {
    return __byte_perm(__byte_perm(q0, q1, 0x0040),
                       __byte_perm(q2, q3, 0x0040), 0x5410);
}

// ---------------------------------------------------------------------------
// Prep: per-tensor max-abs scales + int8 quantize + pack into gQ.
// ---------------------------------------------------------------------------
__global__ void prep_kernel(const float* __restrict__ W1, const float* __restrict__ b1,
                            const float* __restrict__ W2, const float* __restrict__ b2,
                            const float* __restrict__ W3, const float* __restrict__ b3) {
    __shared__ float red[256];
    __shared__ float sS[3];
    const int tid = threadIdx.x;

    const float* Ws[3]  = {W1, W2, W3};
    const int    nel[3] = {64 * 17, 64 * 64, 6 * 64};

    for (int t = 0; t < 3; ++t) {
        float m = 0.0f;
        const float* W = Ws[t];
        for (int i = tid; i < nel[t]; i += 256) m = fmaxf(m, fabsf(W[i]));
        red[tid] = m;
        __syncthreads();
        for (int s = 128; s > 0; s >>= 1) {
            if (tid < s) red[tid] = fmaxf(red[tid], red[tid + s]);
            __syncthreads();
        }
        if (tid == 0) sS[t] = red[0] / QMAXF;
        __syncthreads();
    }

    const float s1 = sS[0], s2 = sS[1], s3 = sS[2];
    const float step = ACT_SCALE / QMAXF;
    if (tid == 0) {
        gQ.G1 = s1;          // (step*s1)/step
        gQ.G2 = s2;
        gQ.G3 = step * s3;
    }
    if (tid < 64) {
        gQ.b1s[tid] = b1[tid] / step;
        gQ.b2s[tid] = b2[tid] / step;
    }
    if (tid < 8) gQ.b3[tid] = (tid < 6) ? b3[tid] : 0.0f;

    // Pack W1: 64 rows x 17 (pad to 20)
    for (int w = tid; w < 64 * 5; w += 256) {
        int j = w / 5, g = w % 5;
        int q[4];
#pragma unroll
        for (int b = 0; b < 4; ++b) {
            int k = 4 * g + b;
            int v = 0;
            if (k < 17) {
                float r = rintf(W1[j * 17 + k] / s1);
                v = (int)fminf(fmaxf(r, -QMAXF), QMAXF);
            }
            q[b] = v;
        }
        gQ.W1[w] = packq(q[0], q[1], q[2], q[3]);
    }
    // Pack W2: 64 x 64
    for (int w = tid; w < 64 * 16; w += 256) {
        int j = w / 16, g = w % 16;
        int q[4];
#pragma unroll
        for (int b = 0; b < 4; ++b) {
            float r = rintf(W2[j * 64 + 4 * g + b] / s2);
            q[b] = (int)fminf(fmaxf(r, -QMAXF), QMAXF);
        }
        gQ.W2[w] = packq(q[0], q[1], q[2], q[3]);
    }
    // Pack W3: 6 x 64
    for (int w = tid; w < 6 * 16; w += 256) {
        int k = w / 16, g = w % 16;
        int q[4];
#pragma unroll
        for (int b = 0; b < 4; ++b) {
            float r = rintf(W3[k * 64 + 4 * g + b] / s3);
            q[b] = (int)fminf(fmaxf(r, -QMAXF), QMAXF);
        }
        gQ.W3[w] = packq(q[0], q[1], q[2], q[3]);
    }
}

// ---------------------------------------------------------------------------
// Main fused MLP kernel: 256 rows/block, one row per thread, DP4A math,
// weights from constant bank.
// ---------------------------------------------------------------------------
__global__ __launch_bounds__(256) void mlp_kernel(
    const float* __restrict__ x, float* __restrict__ out, int B) {

    __shared__ __align__(16) unsigned char sxq[256 * 20];  // packed int8 rows
    __shared__ __align__(16) float sout[256 * 6];

    const int tid  = threadIdx.x;
    const int base = blockIdx.x * 256;
    const int rows = min(256, B - base);

    const float INV = QMAXF / ACT_SCALE;

    // Zero pad region (K 17..19), then quantize+store input bytes.
    for (int i = tid; i < 1280; i += 256) ((int*)sxq)[i] = 0;
    __syncthreads();
    {
        const float* xg = x + base * 17;
        const int n = rows * 17;
        for (int i = tid; i < n; i += 256) {
            float v = xg[i];
            v = fminf(fmaxf(v, -ACT_SCALE), ACT_SCALE);
            int q = __float2int_rn(v * INV);
            int r = i / 17;
            int k = i - r * 17;
            sxq[r * 20 + k] = (unsigned char)q;
        }
    }
    __syncthreads();

    if (tid < rows) {
        const float G1 = cQ.G1, G2 = cQ.G2, G3 = cQ.G3;

        int p0[5];
        {
            const int* rp = (const int*)(sxq + tid * 20);
#pragma unroll
            for (int g = 0; g < 5; ++g) p0[g] = rp[g];
        }

        // ---- layer 1: 17 -> 64, requant, pack ----
        int a1[16];
#pragma unroll
        for (int jw = 0; jw < 16; ++jw) {
            const float4 bb = *(const float4*)&cQ.b1s[jw * 4];
            const float bj[4] = {bb.x, bb.y, bb.z, bb.w};
            int q[4];
#pragma unroll
            for (int jj = 0; jj < 4; ++jj) {
                const int j = jw * 4 + jj;
                int acc = 0;
#pragma unroll
                for (int g = 0; g < 5; ++g) acc = __dp4a(p0[g], cQ.W1[j * 5 + g], acc);
                float f = fmaf((float)acc, G1, bj[jj]);
                int qi = __float2int_rn(f);
                q[jj] = min(max(qi, -127), 127);
            }
            a1[jw] = packq(q[0], q[1], q[2], q[3]);
        }

        // ---- layer 2 (64 -> 64, requant) fused with layer 3 accumulation ----
        int acc3[6] = {0, 0, 0, 0, 0, 0};
#pragma unroll
        for (int jw = 0; jw < 16; ++jw) {
            const float4 bb = *(const float4*)&cQ.b2s[jw * 4];
            const float bj[4] = {bb.x, bb.y, bb.z, bb.w};
            int q[4];
#pragma unroll
            for (int jj = 0; jj < 4; ++jj) {
                const int j = jw * 4 + jj;
                int acc = 0;
#pragma unroll
                for (int g = 0; g < 4; ++g) {
                    const int4 w = *(const int4*)&cQ.W2[j * 16 + g * 4];
                    acc = __dp4a(a1[g * 4 + 0], w.x, acc);
                    acc = __dp4a(a1[g * 4 + 1], w.y, acc);
                    acc = __dp4a(a1[g * 4 + 2], w.z, acc);
                    acc = __dp4a(a1[g * 4 + 3], w.w, acc);
                }
                float f = fmaf((float)acc, G2, bj[jj]);
                int qi = __float2int_rn(f);
                q[jj] = min(max(qi, -127), 127);
            }
            const int a2w = packq(q[0], q[1], q[2], q[3]);
#pragma unroll
            for (int k = 0; k < 6; ++k)
                acc3[k] = __dp4a(a2w, cQ.W3[k * 16 + jw], acc3[k]);
        }

        // ---- layer 3 epilogue ----
#pragma unroll
        for (int k = 0; k < 6; ++k)
            sout[tid * 6 + k] = fmaf((float)acc3[k], G3, cQ.b3[k]);
    }
    __syncthreads();

    // Coalesced output store
    float* og = out + base * 6;
    if (rows == 256) {
        float4* ov = (float4*)og;
        const float4* sv = (const float4*)sout;
        for (int i = tid; i < 384; i += 256) ov[i] = sv[i];
    } else {
        const int nf = rows * 6;
        for (int i = tid; i < nf; i += 256) og[i] = sout[i];
    }
}

extern "C" void kernel_launch(void* const* d_in, const int* in_sizes, int n_in,
                              void* d_out, int out_size) {
    const float* x  = (const float*)d_in[0];
    const float* W1 = (const float*)d_in[1];
    const float* b1 = (const float*)d_in[2];
    const float* W2 = (const float*)d_in[3];
    const float* b2 = (const float*)d_in[4];
    const float* W3 = (const float*)d_in[5];
    const float* b3 = (const float*)d_in[6];
    float* out = (float*)d_out;

    const int B = in_sizes[0] / 17;
    const int blocks = (B + 255) / 256;

    prep_kernel<<<1, 256>>>(W1, b1, W2, b2, W3, b3);

    void* gq_ptr = nullptr;
    cudaGetSymbolAddress(&gq_ptr, gQ);
    cudaMemcpyToSymbolAsync(cQ, gq_ptr, sizeof(QConst), 0,
                            cudaMemcpyDeviceToDevice, 0);

    mlp_kernel<<<blocks, 256>>>(x, out, B);
}